// round 6
// baseline (speedup 1.0000x reference)
#include <cuda_runtime.h>
#include <cuda_bf16.h>
#include <math.h>
#include <stdint.h>

// Problem constants
#define Bn   64
#define Ln   512
#define En   300
#define Pn   200
#define Dn   2800          // P * 2 * M
#define Hn   100
#define Mtot (Bn * Ln)     // 32768
#define NEG  (-100.0f)
#define NINF (-1.0e30f)

// GEMM config: K' = 3*320 (hi|hi|lo vs hi|lo|hi)
#define Kp    320
#define K3    960
#define Np    2816
#define TM    128                // = one L-chunk of one batch row
#define TN    112                // = 8 patterns exactly
#define BK    32                 // bf16 per k-tile
#define NKT   (K3 / BK)          // 30
#define ROWB  80u                // padded smem row stride (bytes) per 32-bf16 row
#define ASZ   (128u * ROWB)      // 10240
#define BSZ   (112u * ROWB)      // 8960
#define STAGE (ASZ + BSZ)        // 19200
#define NSTG  3                  // 57600 bytes of stages
// C staging reuses the stage memory after the K-loop
#define CSTRIDE 114              // floats per C row (pad: 114%32=18 -> conflict-free)
#define CBYTES  (128 * CSTRIDE * 4)       // 58368
#define SMEM_DYN (CBYTES > NSTG * STAGE ? CBYTES : NSTG * STAGE)

// Scan split config
#define NCH  4
#define CL   (Ln / NCH)          // 128

// Scratch (static device globals — no dynamic allocation)
__device__ float                        g_scores[Bn * Pn];
__device__ __align__(256) float         g_part[(size_t)Bn * Pn * NCH * 64];
__device__ __align__(256) __nv_bfloat16 g_A2[(size_t)Mtot * K3];
__device__ __align__(256) __nv_bfloat16 g_B2[(size_t)Np * K3];

// ---------------------------------------------------------------------------
// PTX helpers (baseline PTX only — no 'a'-target instructions)
// ---------------------------------------------------------------------------
__device__ __forceinline__ uint32_t s2u(const void* p) {
    uint32_t a;
    asm("{ .reg .u64 t; cvta.to.shared.u64 t, %1; cvt.u32.u64 %0, t; }"
        : "=r"(a) : "l"(p));
    return a;
}

#define CP_ASYNC16(dst, src) \
    asm volatile("cp.async.cg.shared.global [%0], [%1], 16;" :: "r"(dst), "l"(src) : "memory")
#define CP_COMMIT() asm volatile("cp.async.commit_group;" ::: "memory")
#define CP_WAIT(n)  asm volatile("cp.async.wait_group %0;" :: "n"(n) : "memory")

#define LDSM_X4(r, addr)                                                        \
    asm volatile("ldmatrix.sync.aligned.m8n8.x4.shared.b16 {%0,%1,%2,%3}, [%4];" \
        : "=r"((r)[0]), "=r"((r)[1]), "=r"((r)[2]), "=r"((r)[3]) : "r"(addr))

#define LDSM_X4_B(r0, r1, r2, r3, addr)                                         \
    asm volatile("ldmatrix.sync.aligned.m8n8.x4.shared.b16 {%0,%1,%2,%3}, [%4];" \
        : "=r"(r0), "=r"(r1), "=r"(r2), "=r"(r3) : "r"(addr))

#define LDSM_X2_B(r0, r1, addr)                                                 \
    asm volatile("ldmatrix.sync.aligned.m8n8.x2.shared.b16 {%0,%1}, [%2];"      \
        : "=r"(r0), "=r"(r1) : "r"(addr))

#define MMA_BF16(d, a, b)                                                       \
    asm volatile("mma.sync.aligned.m16n8k16.row.col.f32.bf16.bf16.f32 "         \
        "{%0,%1,%2,%3}, {%4,%5,%6,%7}, {%8,%9}, {%0,%1,%2,%3};"                 \
        : "+f"((d)[0]), "+f"((d)[1]), "+f"((d)[2]), "+f"((d)[3])                \
        : "r"((a)[0]), "r"((a)[1]), "r"((a)[2]), "r"((a)[3]),                   \
          "r"((b)[0]), "r"((b)[1]))

// ---------------------------------------------------------------------------
// Conversion: fp32 -> bf16 hi/lo, A gathered via docs; K padded 300->320
// A2 row = [hi(320) | hi(320) | lo(320)],  B2 row = [hi | lo | hi]
// ---------------------------------------------------------------------------
__global__ void conv_emb_kernel(const int* __restrict__ docs,
                                const float* __restrict__ emb)
{
    const int m = blockIdx.x;
    const int k = threadIdx.x;          // 0..319
    const int doc = docs[m];
    float x = (k < En) ? emb[(size_t)doc * En + k] : 0.0f;
    __nv_bfloat16 hi = __float2bfloat16(x);
    __nv_bfloat16 lo = __float2bfloat16(x - __bfloat162float(hi));
    __nv_bfloat16* row = g_A2 + (size_t)m * K3;
    row[k] = hi;  row[Kp + k] = hi;  row[2 * Kp + k] = lo;
}

__global__ void conv_diag_kernel(const float* __restrict__ diags)
{
    const int d = blockIdx.x;           // 0..2815
    const int k = threadIdx.x;
    float x = (d < Dn && k < En) ? diags[(size_t)d * En + k] : 0.0f;
    __nv_bfloat16 hi = __float2bfloat16(x);
    __nv_bfloat16 lo = __float2bfloat16(x - __bfloat162float(hi));
    __nv_bfloat16* row = g_B2 + (size_t)d * K3;
    row[k] = hi;  row[Kp + k] = lo;  row[2 * Kp + k] = hi;
}

// ---------------------------------------------------------------------------
// Kernel 1: fused bf16 HMMA GEMM + chunk scan.
// CTA = [128 l-positions of one (batch, chunk)] x [8 patterns].
// After the K-loop, C (+bias) is staged to SMEM (reusing the pipeline
// buffers) and 8 warps x 8 lanes compute the max-plus affine transform of
// this chunk (warp = pattern, lane = basis/const column), writing 64 floats
// per (b, p, chunk) to g_part.
// ---------------------------------------------------------------------------
__global__ void __launch_bounds__(256, 2)
gemm_scan_kernel(const float* __restrict__ bias,
                 const float* __restrict__ epsilon)
{
    extern __shared__ char smem[];
    const uint32_t sbase = s2u(smem);

    const int tid  = threadIdx.x;
    const int wid  = tid >> 5;
    const int lane = tid & 31;
    const int wm   = wid & 3;            // 0..3  (M)
    const int wn   = wid >> 2;           // 0..1  (N)
    const int m0   = blockIdx.y * TM;
    const int n0   = blockIdx.x * TN;

    // per-thread ldmatrix offsets (bytes within a stage)
    const uint32_t aoff = (uint32_t)((((lane >> 3) & 1) * 8 + (lane & 7)) * ROWB
                                     + ((lane >> 4) * 8) * 2);
    const uint32_t boff = (uint32_t)(((lane >> 4) * 8 + (lane & 7)) * ROWB
                                     + (((lane >> 3) & 1) * 8) * 2);
    const int l4 = lane & 15;            // x2 uses first 16 lanes' addresses
    const uint32_t boff2 = (uint32_t)((l4 & 7) * ROWB + ((l4 >> 3) * 8) * 2);

    auto load_stage = [&](int buf, int kt) {
        const uint32_t sb = sbase + (uint32_t)buf * STAGE;
        const int kb = kt * BK;
        #pragma unroll
        for (int idx = tid; idx < 512; idx += 256) {    // A: 128 rows x 4 chunks
            const int r = idx >> 2, ch = (idx & 3) * 8;
            CP_ASYNC16(sb + (uint32_t)r * ROWB + (uint32_t)(ch * 2),
                       g_A2 + (size_t)(m0 + r) * K3 + kb + ch);
        }
        for (int idx = tid; idx < 448; idx += 256) {    // B: 112 rows x 4 chunks
            const int r = idx >> 2, ch = (idx & 3) * 8;
            CP_ASYNC16(sb + ASZ + (uint32_t)r * ROWB + (uint32_t)(ch * 2),
                       g_B2 + (size_t)(n0 + r) * K3 + kb + ch);
        }
        CP_COMMIT();
    };

    float c[2][7][4];
    #pragma unroll
    for (int i = 0; i < 2; i++)
        #pragma unroll
        for (int j = 0; j < 7; j++)
            #pragma unroll
            for (int q = 0; q < 4; q++) c[i][j][q] = 0.f;

    load_stage(0, 0);
    load_stage(1, 1);

    for (int kt = 0; kt < NKT; kt++) {
        if (kt < NKT - 1) CP_WAIT(1);
        else              CP_WAIT(0);
        __syncthreads();

        if (kt + 2 < NKT) load_stage((kt + 2) % NSTG, kt + 2);

        const uint32_t sA = sbase + (uint32_t)(kt % NSTG) * STAGE;
        const uint32_t sB = sA + ASZ;
        #pragma unroll
        for (int ks = 0; ks < 2; ks++) {
            uint32_t a[2][4], bfr[7][2];
            #pragma unroll
            for (int i = 0; i < 2; i++)
                LDSM_X4(a[i], sA + (uint32_t)((wm * 32 + i * 16) * ROWB) + (uint32_t)(ks * 32) + aoff);
            #pragma unroll
            for (int j2 = 0; j2 < 3; j2++)
                LDSM_X4_B(bfr[j2 * 2][0], bfr[j2 * 2][1],
                          bfr[j2 * 2 + 1][0], bfr[j2 * 2 + 1][1],
                          sB + (uint32_t)((wn * 56 + j2 * 16) * ROWB) + (uint32_t)(ks * 32) + boff);
            LDSM_X2_B(bfr[6][0], bfr[6][1],
                      sB + (uint32_t)((wn * 56 + 48) * ROWB) + (uint32_t)(ks * 32) + boff2);
            #pragma unroll
            for (int i = 0; i < 2; i++)
                #pragma unroll
                for (int j = 0; j < 7; j++)
                    MMA_BF16(c[i][j], a[i], bfr[j]);
        }
    }

    // ---- stage C (+bias) into SMEM, reusing the dead pipeline buffers ----
    __syncthreads();   // all ldmatrix reads done before overwrite
    float* Cs = reinterpret_cast<float*>(smem);
    const int gid = lane >> 2;
    const int tig = lane & 3;
    #pragma unroll
    for (int i = 0; i < 2; i++) {
        const int r0 = wm * 32 + i * 16 + gid;
        #pragma unroll
        for (int j = 0; j < 7; j++) {
            const int col = wn * 56 + j * 8 + tig * 2;
            const float bx = __ldg(bias + n0 + col);
            const float by = __ldg(bias + n0 + col + 1);
            *reinterpret_cast<float2*>(Cs + r0 * CSTRIDE + col) =
                make_float2(c[i][j][0] + bx, c[i][j][1] + by);
            *reinterpret_cast<float2*>(Cs + (r0 + 8) * CSTRIDE + col) =
                make_float2(c[i][j][2] + bx, c[i][j][3] + by);
        }
    }
    __syncthreads();

    // ---- chunk scan: warp = pattern, lanes 0..7 = affine columns ----
    if (lane < 8) {
        const int p     = blockIdx.x * 8 + wid;
        const int b     = m0 >> 9;           // batch
        const int chunk = (m0 >> 7) & 3;     // L-chunk

        float e[6];
        #pragma unroll
        for (int k = 0; k < 6; k++) e[k] = __ldg(epsilon + p * 6 + k);

        float h[7];
        #pragma unroll
        for (int i = 0; i < 7; i++) h[i] = NINF;
        if (lane < 7) h[lane] = 0.0f;
        float smax = NINF;
        const bool is_const = (lane == 7);

        const float* Cp = Cs + wid * 14;
        for (int l = 0; l < CL; l++) {
            const float* x = Cp + l * CSTRIDE;
            float xv[14];
            #pragma unroll
            for (int q = 0; q < 7; q++) {
                float2 v = *reinterpret_cast<const float2*>(x + 2 * q);
                xv[2 * q] = v.x;  xv[2 * q + 1] = v.y;
            }
            float ae[7];
            ae[0] = is_const ? fmaxf(h[0], NEG) : h[0];
            #pragma unroll
            for (int m = 1; m < 7; m++)
                ae[m] = fmaxf(h[m], h[m - 1] + e[m - 1]);
            float nh[7];
            nh[0] = ae[0] + xv[0];
            if (is_const) nh[0] = fmaxf(0.0f, nh[0]);
            #pragma unroll
            for (int m = 1; m < 7; m++)
                nh[m] = fmaxf(ae[m - 1] + xv[7 + (m - 1)], ae[m] + xv[m]);
            smax = fmaxf(smax, nh[6]);
            #pragma unroll
            for (int m = 0; m < 7; m++) h[m] = nh[m];
        }

        float* slot = g_part + ((size_t)(b * Pn + p) * NCH + chunk) * 64;
        if (lane < 7) {
            #pragma unroll
            for (int i = 0; i < 7; i++) slot[lane * 7 + i] = h[i];
            slot[56 + lane] = smax;
        } else {
            #pragma unroll
            for (int i = 0; i < 7; i++) slot[49 + i] = h[i];
            slot[63] = smax;
        }
    }
}

// ---------------------------------------------------------------------------
// Kernel 2: combine the 4 chunk transforms per chain.
// ---------------------------------------------------------------------------
__global__ void scan_combine_kernel()
{
    const int bp = blockIdx.x * blockDim.x + threadIdx.x;
    if (bp >= Bn * Pn) return;

    float h[7];
    h[0] = 0.0f;
    #pragma unroll
    for (int i = 1; i < 7; i++) h[i] = NEG;
    float s = NEG;

    #pragma unroll 1
    for (int c = 0; c < NCH; c++) {
        const float* sl = g_part + ((size_t)bp * NCH + c) * 64;
        float ns = fmaxf(s, sl[63]);               // const-column S
        #pragma unroll
        for (int j = 0; j < 7; j++) ns = fmaxf(ns, sl[56 + j] + h[j]);
        float nh[7];
        #pragma unroll
        for (int i = 0; i < 7; i++) {
            float v = sl[49 + i];                  // const column
            #pragma unroll
            for (int j = 0; j < 7; j++) v = fmaxf(v, sl[j * 7 + i] + h[j]);
            nh[i] = v;
        }
        #pragma unroll
        for (int i = 0; i < 7; i++) h[i] = nh[i];
        s = ns;
    }
    g_scores[bp] = s;
}

// ---------------------------------------------------------------------------
// Kernel 3: MLP + log_softmax. One block per batch row.
// ---------------------------------------------------------------------------
__global__ void mlp_kernel(const float* __restrict__ w1, const float* __restrict__ b1,
                           const float* __restrict__ w2, const float* __restrict__ b2,
                           const float* __restrict__ w3, const float* __restrict__ b3,
                           float* __restrict__ out)
{
    const int b = blockIdx.x;
    const int tid = threadIdx.x;
    __shared__ float sc[Pn];
    __shared__ float h1[Hn];
    __shared__ float h2[Hn];

    for (int i = tid; i < Pn; i += blockDim.x) sc[i] = g_scores[b * Pn + i];
    __syncthreads();

    if (tid < Hn) {
        float acc = b1[tid];
        #pragma unroll 4
        for (int p = 0; p < Pn; p++) acc = fmaf(sc[p], w1[p * Hn + tid], acc);
        h1[tid] = fmaxf(acc, 0.f);
    }
    __syncthreads();

    if (tid < Hn) {
        float acc = b2[tid];
        #pragma unroll 4
        for (int j = 0; j < Hn; j++) acc = fmaf(h1[j], w2[j * Hn + tid], acc);
        h2[tid] = fmaxf(acc, 0.f);
    }
    __syncthreads();

    if (tid == 0) {
        float l0 = b3[0], l1 = b3[1];
        for (int j = 0; j < Hn; j++) {
            l0 = fmaf(h2[j], w3[j * 2 + 0], l0);
            l1 = fmaf(h2[j], w3[j * 2 + 1], l1);
        }
        float mx  = fmaxf(l0, l1);
        float lse = mx + logf(expf(l0 - mx) + expf(l1 - mx));
        out[b * 2 + 0] = l0 - lse;
        out[b * 2 + 1] = l1 - lse;
    }
}

// ---------------------------------------------------------------------------
extern "C" void kernel_launch(void* const* d_in, const int* in_sizes, int n_in,
                              void* d_out, int out_size)
{
    const int*   docs    = (const int*)  d_in[0];
    const float* emb     = (const float*)d_in[1];
    const float* diags   = (const float*)d_in[2];
    const float* bias    = (const float*)d_in[3];
    const float* epsilon = (const float*)d_in[4];
    const float* w1      = (const float*)d_in[5];
    const float* b1      = (const float*)d_in[6];
    const float* w2      = (const float*)d_in[7];
    const float* b2      = (const float*)d_in[8];
    const float* w3      = (const float*)d_in[9];
    const float* b3      = (const float*)d_in[10];
    float* out = (float*)d_out;

    cudaFuncSetAttribute(gemm_scan_kernel,
                         cudaFuncAttributeMaxDynamicSharedMemorySize, SMEM_DYN);

    conv_emb_kernel<<<Mtot, Kp>>>(docs, emb);
    conv_diag_kernel<<<Np, Kp>>>(diags);

    dim3 gridG(Dn / TN, Mtot / TM);   // (25, 256)
    gemm_scan_kernel<<<gridG, 256, SMEM_DYN>>>(bias, epsilon);

    scan_combine_kernel<<<(Bn * Pn + 127) / 128, 128>>>();

    mlp_kernel<<<Bn, 128>>>(w1, b1, w2, b2, w3, b3, out);
}

// round 7
// speedup vs baseline: 1.0647x; 1.0647x over previous
#include <cuda_runtime.h>
#include <cuda_bf16.h>
#include <math.h>
#include <stdint.h>

// Problem constants
#define Bn   64
#define Ln   512
#define En   300
#define Pn   200
#define Dn   2800          // P * 2 * M
#define Hn   100
#define Mtot (Bn * Ln)     // 32768
#define NEG  (-100.0f)
#define NINF (-1.0e30f)

// GEMM config: logical K' = 3*320 (hi*hi, hi*lo, lo*hi), stored K2 = 2*320
#define Kp    320
#define K2    640
#define Np    2816
#define TM    128
#define TN    128
#define BK    32                 // bf16 per k-tile
#define NKT   30                 // 3 terms x 10 chunks
#define ROWB  80u                // padded smem row stride (bytes) per 32-bf16 row
#define ASZ   (128u * ROWB)      // 10240
#define STAGE (2u * ASZ)         // A + B = 20480
#define NSTG  3
#define SMEM_DYN (NSTG * STAGE)  // 61440

// Scan split config
#define NCH  8
#define CL   (Ln / NCH)          // 64

// Scratch (static device globals — no dynamic allocation)
__device__ float                        g_scores[Bn * Pn];
__device__ __align__(256) float         g_ts2[(size_t)Bn * Pn * Ln * 16]; // scan layout
__device__ __align__(256) float         g_part[(size_t)Bn * Pn * NCH * 64];
__device__ __align__(256) __nv_bfloat16 g_A2[(size_t)Mtot * K2];
__device__ __align__(256) __nv_bfloat16 g_B2[(size_t)Np * K2];

// ---------------------------------------------------------------------------
// PTX helpers (baseline PTX only — no 'a'-target instructions)
// ---------------------------------------------------------------------------
__device__ __forceinline__ uint32_t s2u(const void* p) {
    uint32_t a;
    asm("{ .reg .u64 t; cvta.to.shared.u64 t, %1; cvt.u32.u64 %0, t; }"
        : "=r"(a) : "l"(p));
    return a;
}

#define CP_ASYNC16(dst, src) \
    asm volatile("cp.async.cg.shared.global [%0], [%1], 16;" :: "r"(dst), "l"(src) : "memory")
#define CP_COMMIT() asm volatile("cp.async.commit_group;" ::: "memory")
#define CP_WAIT(n)  asm volatile("cp.async.wait_group %0;" :: "n"(n) : "memory")

#define LDSM_X4(r, addr)                                                        \
    asm volatile("ldmatrix.sync.aligned.m8n8.x4.shared.b16 {%0,%1,%2,%3}, [%4];" \
        : "=r"((r)[0]), "=r"((r)[1]), "=r"((r)[2]), "=r"((r)[3]) : "r"(addr))

#define LDSM_X4_B(r0, r1, r2, r3, addr)                                         \
    asm volatile("ldmatrix.sync.aligned.m8n8.x4.shared.b16 {%0,%1,%2,%3}, [%4];" \
        : "=r"(r0), "=r"(r1), "=r"(r2), "=r"(r3) : "r"(addr))

#define MMA_BF16(d, a, b)                                                       \
    asm volatile("mma.sync.aligned.m16n8k16.row.col.f32.bf16.bf16.f32 "         \
        "{%0,%1,%2,%3}, {%4,%5,%6,%7}, {%8,%9}, {%0,%1,%2,%3};"                 \
        : "+f"((d)[0]), "+f"((d)[1]), "+f"((d)[2]), "+f"((d)[3])                \
        : "r"((a)[0]), "r"((a)[1]), "r"((a)[2]), "r"((a)[3]),                   \
          "r"((b)[0]), "r"((b)[1]))

// ---------------------------------------------------------------------------
// Conversion: fp32 -> bf16 hi/lo; rows are [hi(320) | lo(320)]
// ---------------------------------------------------------------------------
__global__ void conv_emb_kernel(const int* __restrict__ docs,
                                const float* __restrict__ emb)
{
    const int m = blockIdx.x;
    const int k = threadIdx.x;          // 0..319
    const int doc = docs[m];
    float x = (k < En) ? emb[(size_t)doc * En + k] : 0.0f;
    __nv_bfloat16 hi = __float2bfloat16(x);
    __nv_bfloat16 lo = __float2bfloat16(x - __bfloat162float(hi));
    __nv_bfloat16* row = g_A2 + (size_t)m * K2;
    row[k] = hi;  row[Kp + k] = lo;
}

__global__ void conv_diag_kernel(const float* __restrict__ diags)
{
    const int d = blockIdx.x;           // 0..2815
    const int k = threadIdx.x;
    float x = (d < Dn && k < En) ? diags[(size_t)d * En + k] : 0.0f;
    __nv_bfloat16 hi = __float2bfloat16(x);
    __nv_bfloat16 lo = __float2bfloat16(x - __bfloat162float(hi));
    __nv_bfloat16* row = g_B2 + (size_t)d * K2;
    row[k] = hi;  row[Kp + k] = lo;
}

// ---------------------------------------------------------------------------
// Kernel 1: bf16 HMMA GEMM, C[m,n] = sum of 3 split terms + bias[n]
// Term t = kt/10: A uses {hi,hi,lo}[t], B uses {hi,lo,hi}[t].
// 128x128 tile, BK=32, 3-stage cp.async, warp tile 32x64, 2 CTAs/SM.
// Epilogue writes directly into scan layout [B][P][L][16].
// ---------------------------------------------------------------------------
__global__ void __launch_bounds__(256, 2)
gemm_hmma_kernel(const float* __restrict__ bias)
{
    extern __shared__ char smem[];
    const uint32_t sbase = s2u(smem);

    const int tid  = threadIdx.x;
    const int wid  = tid >> 5;
    const int lane = tid & 31;
    const int wm   = wid & 3;            // 0..3  (M)
    const int wn   = wid >> 2;           // 0..1  (N)
    const int m0   = blockIdx.y * TM;
    const int n0   = blockIdx.x * TN;

    const uint32_t aoff = (uint32_t)((((lane >> 3) & 1) * 8 + (lane & 7)) * ROWB
                                     + ((lane >> 4) * 8) * 2);
    const uint32_t boff = (uint32_t)(((lane >> 4) * 8 + (lane & 7)) * ROWB
                                     + (((lane >> 3) & 1) * 8) * 2);

    const int cr0 = tid >> 2;            // rows 0..63 for t=0, +64 for t=1
    const int cc  = (tid & 3) * 8;       // bf16 col offset (0,8,16,24)

    auto load_stage = [&](int buf, int kt) {
        const uint32_t sb = sbase + (uint32_t)buf * STAGE;
        const int t  = kt / 10;
        const int kk = (kt - t * 10) * BK;
        const int ak = (t == 2 ? Kp : 0) + kk;   // A: hi, hi, lo
        const int bk = (t == 1 ? Kp : 0) + kk;   // B: hi, lo, hi
        #pragma unroll
        for (int u = 0; u < 2; u++) {
            const int r = cr0 + u * 64;
            CP_ASYNC16(sb + (uint32_t)r * ROWB + (uint32_t)(cc * 2),
                       g_A2 + (size_t)(m0 + r) * K2 + ak + cc);
        }
        #pragma unroll
        for (int u = 0; u < 2; u++) {
            const int r = cr0 + u * 64;
            CP_ASYNC16(sb + ASZ + (uint32_t)r * ROWB + (uint32_t)(cc * 2),
                       g_B2 + (size_t)(n0 + r) * K2 + bk + cc);
        }
        CP_COMMIT();
    };

    float c[2][8][4];
    #pragma unroll
    for (int i = 0; i < 2; i++)
        #pragma unroll
        for (int j = 0; j < 8; j++)
            #pragma unroll
            for (int q = 0; q < 4; q++) c[i][j][q] = 0.f;

    load_stage(0, 0);
    load_stage(1, 1);

    for (int kt = 0; kt < NKT; kt++) {
        if (kt < NKT - 1) CP_WAIT(1);
        else              CP_WAIT(0);
        __syncthreads();

        if (kt + 2 < NKT) load_stage((kt + 2) % NSTG, kt + 2);

        const uint32_t sA = sbase + (uint32_t)(kt % NSTG) * STAGE;
        const uint32_t sB = sA + ASZ;
        #pragma unroll
        for (int ks = 0; ks < 2; ks++) {
            uint32_t a[2][4], bfr[8][2];
            #pragma unroll
            for (int i = 0; i < 2; i++)
                LDSM_X4(a[i], sA + (uint32_t)((wm * 32 + i * 16) * ROWB) + (uint32_t)(ks * 32) + aoff);
            #pragma unroll
            for (int j2 = 0; j2 < 4; j2++)
                LDSM_X4_B(bfr[j2 * 2][0], bfr[j2 * 2][1],
                          bfr[j2 * 2 + 1][0], bfr[j2 * 2 + 1][1],
                          sB + (uint32_t)((wn * 64 + j2 * 16) * ROWB) + (uint32_t)(ks * 32) + boff);
            #pragma unroll
            for (int i = 0; i < 2; i++)
                #pragma unroll
                for (int j = 0; j < 8; j++)
                    MMA_BF16(c[i][j], a[i], bfr[j]);
        }
    }

    // ---- epilogue: write into scan layout [B][P][L][16] ----
    const int gid = lane >> 2;
    const int tig = lane & 3;
    #pragma unroll
    for (int i = 0; i < 2; i++) {
        const int mr = m0 + wm * 32 + i * 16 + gid;   // + {0,8}
        #pragma unroll
        for (int j = 0; j < 8; j++) {
            const int n  = n0 + wn * 64 + j * 8 + tig * 2;
            const int p  = n / 14;
            const int jj = n - p * 14;                // even, pair stays within p
            if (p < Pn) {
                const float bx = __ldg(bias + n);
                const float by = __ldg(bias + n + 1);
                #pragma unroll
                for (int h = 0; h < 2; h++) {
                    const int m = mr + h * 8;
                    const int b = m >> 9, l = m & 511;
                    float* dst = g_ts2 + (((size_t)(b * Pn + p) * Ln + l) << 4) + jj;
                    float2 v = make_float2(c[i][j][h * 2] + bx, c[i][j][h * 2 + 1] + by);
                    *reinterpret_cast<float2*>(dst) = v;
                }
            }
        }
    }
}

// ---------------------------------------------------------------------------
// Kernel 2a: chunked max-plus scan (8 chunks per chain for latency hiding).
// Slot layout (64 floats): [0..48] M cols j*7+i, [49..55] C, [56..63] S.
// ---------------------------------------------------------------------------
__global__ void __launch_bounds__(128, 4)
scan_part_kernel(const float* __restrict__ epsilon)
{
    const int id = blockIdx.x * blockDim.x + threadIdx.x;
    if (id >= Bn * Pn * NCH) return;
    const int c  = id & (NCH - 1);
    const int bp = id >> 3;
    const int p  = bp % Pn;

    float e[6];
    #pragma unroll
    for (int j = 0; j < 6; j++) e[j] = __ldg(epsilon + p * 6 + j);

    float h[8][7];
    #pragma unroll
    for (int j = 0; j < 8; j++)
        #pragma unroll
        for (int i = 0; i < 7; i++) h[j][i] = NINF;
    #pragma unroll
    for (int j = 0; j < 7; j++) h[j][j] = 0.0f;
    float smax[8];
    #pragma unroll
    for (int j = 0; j < 8; j++) smax[j] = NINF;

    const float4* base = reinterpret_cast<const float4*>(
        g_ts2 + (((size_t)bp * Ln + c * CL) << 4));

    float4 nx[2][4];
    #pragma unroll
    for (int u = 0; u < 2; u++)
        #pragma unroll
        for (int q = 0; q < 4; q++) nx[u][q] = base[u * 4 + q];

    for (int l = 0; l < CL; l += 2) {
        float4 cur[2][4];
        #pragma unroll
        for (int u = 0; u < 2; u++)
            #pragma unroll
            for (int q = 0; q < 4; q++) cur[u][q] = nx[u][q];
        if (l + 2 < CL) {
            const float4* nb = base + (size_t)(l + 2) * 4;
            #pragma unroll
            for (int u = 0; u < 2; u++)
                #pragma unroll
                for (int q = 0; q < 4; q++) nx[u][q] = nb[u * 4 + q];
        }

        #pragma unroll
        for (int u = 0; u < 2; u++) {
            float xv[14];
            xv[0]  = cur[u][0].x;  xv[1]  = cur[u][0].y;  xv[2]  = cur[u][0].z;  xv[3]  = cur[u][0].w;
            xv[4]  = cur[u][1].x;  xv[5]  = cur[u][1].y;  xv[6]  = cur[u][1].z;  xv[7]  = cur[u][1].w;
            xv[8]  = cur[u][2].x;  xv[9]  = cur[u][2].y;  xv[10] = cur[u][2].z;  xv[11] = cur[u][2].w;
            xv[12] = cur[u][3].x;  xv[13] = cur[u][3].y;

            #pragma unroll
            for (int j = 0; j < 8; j++) {
                float ae[7];
                ae[0] = (j == 7) ? fmaxf(h[j][0], NEG) : h[j][0];
                #pragma unroll
                for (int m = 1; m < 7; m++)
                    ae[m] = fmaxf(h[j][m], h[j][m - 1] + e[m - 1]);
                float nh[7];
                nh[0] = ae[0] + xv[0];
                if (j == 7) nh[0] = fmaxf(0.0f, nh[0]);
                #pragma unroll
                for (int m = 1; m < 7; m++)
                    nh[m] = fmaxf(ae[m - 1] + xv[7 + (m - 1)], ae[m] + xv[m]);
                smax[j] = fmaxf(smax[j], nh[6]);
                #pragma unroll
                for (int m = 0; m < 7; m++) h[j][m] = nh[m];
            }
        }
    }

    float* slot = g_part + (size_t)id * 64;
    #pragma unroll
    for (int j = 0; j < 7; j++)
        #pragma unroll
        for (int i = 0; i < 7; i++) slot[j * 7 + i] = h[j][i];
    #pragma unroll
    for (int i = 0; i < 7; i++) slot[49 + i] = h[7][i];
    #pragma unroll
    for (int j = 0; j < 8; j++) slot[56 + j] = smax[j];
}

// ---------------------------------------------------------------------------
// Kernel 2b: combine the NCH chunk transforms per chain.
// ---------------------------------------------------------------------------
__global__ void scan_combine_kernel()
{
    const int bp = blockIdx.x * blockDim.x + threadIdx.x;
    if (bp >= Bn * Pn) return;

    float h[7];
    h[0] = 0.0f;
    #pragma unroll
    for (int i = 1; i < 7; i++) h[i] = NEG;
    float s = NEG;

    #pragma unroll 1
    for (int c = 0; c < NCH; c++) {
        const float* sl = g_part + ((size_t)bp * NCH + c) * 64;
        float ns = fmaxf(s, sl[63]);               // const-column S
        #pragma unroll
        for (int j = 0; j < 7; j++) ns = fmaxf(ns, sl[56 + j] + h[j]);
        float nh[7];
        #pragma unroll
        for (int i = 0; i < 7; i++) {
            float v = sl[49 + i];                  // const column
            #pragma unroll
            for (int j = 0; j < 7; j++) v = fmaxf(v, sl[j * 7 + i] + h[j]);
            nh[i] = v;
        }
        #pragma unroll
        for (int i = 0; i < 7; i++) h[i] = nh[i];
        s = ns;
    }
    g_scores[bp] = s;
}

// ---------------------------------------------------------------------------
// Kernel 3: MLP + log_softmax. One block per batch row.
// ---------------------------------------------------------------------------
__global__ void mlp_kernel(const float* __restrict__ w1, const float* __restrict__ b1,
                           const float* __restrict__ w2, const float* __restrict__ b2,
                           const float* __restrict__ w3, const float* __restrict__ b3,
                           float* __restrict__ out)
{
    const int b = blockIdx.x;
    const int tid = threadIdx.x;
    __shared__ float sc[Pn];
    __shared__ float h1[Hn];
    __shared__ float h2[Hn];

    for (int i = tid; i < Pn; i += blockDim.x) sc[i] = g_scores[b * Pn + i];
    __syncthreads();

    if (tid < Hn) {
        float acc = b1[tid];
        #pragma unroll 4
        for (int p = 0; p < Pn; p++) acc = fmaf(sc[p], w1[p * Hn + tid], acc);
        h1[tid] = fmaxf(acc, 0.f);
    }
    __syncthreads();

    if (tid < Hn) {
        float acc = b2[tid];
        #pragma unroll 4
        for (int j = 0; j < Hn; j++) acc = fmaf(h1[j], w2[j * Hn + tid], acc);
        h2[tid] = fmaxf(acc, 0.f);
    }
    __syncthreads();

    if (tid == 0) {
        float l0 = b3[0], l1 = b3[1];
        for (int j = 0; j < Hn; j++) {
            l0 = fmaf(h2[j], w3[j * 2 + 0], l0);
            l1 = fmaf(h2[j], w3[j * 2 + 1], l1);
        }
        float mx  = fmaxf(l0, l1);
        float lse = mx + logf(expf(l0 - mx) + expf(l1 - mx));
        out[b * 2 + 0] = l0 - lse;
        out[b * 2 + 1] = l1 - lse;
    }
}

// ---------------------------------------------------------------------------
extern "C" void kernel_launch(void* const* d_in, const int* in_sizes, int n_in,
                              void* d_out, int out_size)
{
    const int*   docs    = (const int*)  d_in[0];
    const float* emb     = (const float*)d_in[1];
    const float* diags   = (const float*)d_in[2];
    const float* bias    = (const float*)d_in[3];
    const float* epsilon = (const float*)d_in[4];
    const float* w1      = (const float*)d_in[5];
    const float* b1      = (const float*)d_in[6];
    const float* w2      = (const float*)d_in[7];
    const float* b2      = (const float*)d_in[8];
    const float* w3      = (const float*)d_in[9];
    const float* b3      = (const float*)d_in[10];
    float* out = (float*)d_out;

    cudaFuncSetAttribute(gemm_hmma_kernel,
                         cudaFuncAttributeMaxDynamicSharedMemorySize, SMEM_DYN);

    conv_emb_kernel<<<Mtot, Kp>>>(docs, emb);
    conv_diag_kernel<<<Np, Kp>>>(diags);

    dim3 gridG(Np / TN, Mtot / TM);   // (22, 256)
    gemm_hmma_kernel<<<gridG, 256, SMEM_DYN>>>(bias);

    scan_part_kernel<<<(Bn * Pn * NCH + 127) / 128, 128>>>(epsilon);
    scan_combine_kernel<<<(Bn * Pn + 127) / 128, 128>>>();

    mlp_kernel<<<Bn, 128>>>(w1, b1, w2, b2, w3, b3, out);
}

// round 8
// speedup vs baseline: 1.3214x; 1.2411x over previous
#include <cuda_runtime.h>
#include <cuda_bf16.h>
#include <math.h>
#include <stdint.h>

// Problem constants
#define Bn   64
#define Ln   512
#define En   300
#define Vv   50000
#define Pn   200
#define Dn   2800          // P * 2 * M
#define Hn   100
#define Mtot (Bn * Ln)     // 32768
#define NEG  (-100.0f)
#define NINF (-1.0e30f)

// GEMM config: logical K' = 3*320 (hi*hi, hi*lo, lo*hi), stored K2 = 2*320
#define Kp    320
#define K2    640
#define Np    2816
#define TM    128
#define TN    128
#define BK    32                 // bf16 per k-tile
#define NKT   30                 // 3 terms x 10 chunks
#define ROWB  80u                // padded smem row stride (bytes) per 32-bf16 row
#define ASZ   (128u * ROWB)      // 10240
#define STAGE (2u * ASZ)         // A + B = 20480
#define NSTG  3
#define SMEM_DYN (NSTG * STAGE)  // 61440

// Scan split config
#define NCH   4
#define CL    (Ln / NCH)         // 128
#define PPB   100                // patterns per scan block
#define PSPL  2

// Scratch (static device globals — no dynamic allocation)
__device__ float                        g_scores[Bn * Pn];
__device__ __align__(256) float         g_tsu[(size_t)Mtot * Np];  // [uid][n]
__device__ __align__(256) float         g_part[(size_t)Bn * Pn * NCH * 64];
__device__ __align__(256) __nv_bfloat16 g_A2[(size_t)Mtot * K2];
__device__ __align__(256) __nv_bfloat16 g_B2[(size_t)Np * K2];
__device__ int g_flag[Vv];
__device__ int g_tok[Mtot];
__device__ int g_uid[Mtot];
__device__ int g_count;

// ---------------------------------------------------------------------------
// PTX helpers (baseline PTX only — no 'a'-target instructions)
// ---------------------------------------------------------------------------
__device__ __forceinline__ uint32_t s2u(const void* p) {
    uint32_t a;
    asm("{ .reg .u64 t; cvta.to.shared.u64 t, %1; cvt.u32.u64 %0, t; }"
        : "=r"(a) : "l"(p));
    return a;
}

#define CP_ASYNC16(dst, src) \
    asm volatile("cp.async.cg.shared.global [%0], [%1], 16;" :: "r"(dst), "l"(src) : "memory")
#define CP_COMMIT() asm volatile("cp.async.commit_group;" ::: "memory")
#define CP_WAIT(n)  asm volatile("cp.async.wait_group %0;" :: "n"(n) : "memory")

#define LDSM_X4(r, addr)                                                        \
    asm volatile("ldmatrix.sync.aligned.m8n8.x4.shared.b16 {%0,%1,%2,%3}, [%4];" \
        : "=r"((r)[0]), "=r"((r)[1]), "=r"((r)[2]), "=r"((r)[3]) : "r"(addr))

#define LDSM_X4_B(r0, r1, r2, r3, addr)                                         \
    asm volatile("ldmatrix.sync.aligned.m8n8.x4.shared.b16 {%0,%1,%2,%3}, [%4];" \
        : "=r"(r0), "=r"(r1), "=r"(r2), "=r"(r3) : "r"(addr))

#define MMA_BF16(d, a, b)                                                       \
    asm volatile("mma.sync.aligned.m16n8k16.row.col.f32.bf16.bf16.f32 "         \
        "{%0,%1,%2,%3}, {%4,%5,%6,%7}, {%8,%9}, {%0,%1,%2,%3};"                 \
        : "+f"((d)[0]), "+f"((d)[1]), "+f"((d)[2]), "+f"((d)[3])                \
        : "r"((a)[0]), "r"((a)[1]), "r"((a)[2]), "r"((a)[3]),                   \
          "r"((b)[0]), "r"((b)[1]))

// ---------------------------------------------------------------------------
// Dedup: flag -> prefix scan (deterministic) -> uid maps
// ---------------------------------------------------------------------------
__global__ void dedup_clear_kernel() {
    const int i = blockIdx.x * blockDim.x + threadIdx.x;
    if (i < Vv) g_flag[i] = 0;
}
__global__ void dedup_mark_kernel(const int* __restrict__ docs) {
    const int m = blockIdx.x * blockDim.x + threadIdx.x;
    if (m < Mtot) g_flag[docs[m]] = 1;       // racing writes of 1: benign
}
__global__ void __launch_bounds__(1024) dedup_scan_kernel() {
    __shared__ int ss[1024];
    const int tid = threadIdx.x;
    const int CHUNK = (Vv + 1023) / 1024;    // 49
    const int base = tid * CHUNK;
    int s = 0;
    for (int i = 0; i < CHUNK; i++) {
        const int v = base + i;
        if (v < Vv) s += g_flag[v];
    }
    ss[tid] = s;
    __syncthreads();
    for (int off = 1; off < 1024; off <<= 1) {
        int v = (tid >= off) ? ss[tid - off] : 0;
        __syncthreads();
        ss[tid] += v;
        __syncthreads();
    }
    int run = (tid == 0) ? 0 : ss[tid - 1];
    if (tid == 1023) g_count = ss[1023];
    for (int i = 0; i < CHUNK; i++) {
        const int v = base + i;
        if (v < Vv && g_flag[v]) {
            g_tok[run] = v;
            g_flag[v] = run + 1;             // uid+1 (0 = unused)
            run++;
        }
    }
}
__global__ void dedup_uid_kernel(const int* __restrict__ docs) {
    const int m = blockIdx.x * blockDim.x + threadIdx.x;
    if (m < Mtot) g_uid[m] = g_flag[docs[m]] - 1;
}

// ---------------------------------------------------------------------------
// Conversion: fp32 -> bf16 hi/lo; rows are [hi(320) | lo(320)]
// ---------------------------------------------------------------------------
__global__ void conv_emb_kernel(const float* __restrict__ emb)
{
    const int u = blockIdx.x;
    if (u >= g_count) return;
    const int k = threadIdx.x;          // 0..319
    const int tok = g_tok[u];
    float x = (k < En) ? emb[(size_t)tok * En + k] : 0.0f;
    __nv_bfloat16 hi = __float2bfloat16(x);
    __nv_bfloat16 lo = __float2bfloat16(x - __bfloat162float(hi));
    __nv_bfloat16* row = g_A2 + (size_t)u * K2;
    row[k] = hi;  row[Kp + k] = lo;
}

__global__ void conv_diag_kernel(const float* __restrict__ diags)
{
    const int d = blockIdx.x;           // 0..2815
    const int k = threadIdx.x;
    float x = (d < Dn && k < En) ? diags[(size_t)d * En + k] : 0.0f;
    __nv_bfloat16 hi = __float2bfloat16(x);
    __nv_bfloat16 lo = __float2bfloat16(x - __bfloat162float(hi));
    __nv_bfloat16* row = g_B2 + (size_t)d * K2;
    row[k] = hi;  row[Kp + k] = lo;
}

// ---------------------------------------------------------------------------
// Kernel 1: bf16 HMMA GEMM over uid rows.  ts_u[u,n] = A2[u]·B2[n] + bias[n]
// Term t = kt/10: A uses {hi,hi,lo}[t], B uses {hi,lo,hi}[t].
// ---------------------------------------------------------------------------
__global__ void __launch_bounds__(256, 2)
gemm_hmma_kernel(const float* __restrict__ bias)
{
    const int m0 = blockIdx.y * TM;
    const int cnt = g_count;
    if (m0 >= cnt) return;              // uniform per-CTA exit

    extern __shared__ char smem[];
    const uint32_t sbase = s2u(smem);

    const int tid  = threadIdx.x;
    const int wid  = tid >> 5;
    const int lane = tid & 31;
    const int wm   = wid & 3;            // 0..3  (M)
    const int wn   = wid >> 2;           // 0..1  (N)
    const int n0   = blockIdx.x * TN;

    const uint32_t aoff = (uint32_t)((((lane >> 3) & 1) * 8 + (lane & 7)) * ROWB
                                     + ((lane >> 4) * 8) * 2);
    const uint32_t boff = (uint32_t)(((lane >> 4) * 8 + (lane & 7)) * ROWB
                                     + (((lane >> 3) & 1) * 8) * 2);

    const int cr0 = tid >> 2;            // rows 0..63 (+64)
    const int cc  = (tid & 3) * 8;       // bf16 col offset

    auto load_stage = [&](int buf, int kt) {
        const uint32_t sb = sbase + (uint32_t)buf * STAGE;
        const int t  = kt / 10;
        const int kk = (kt - t * 10) * BK;
        const int ak = (t == 2 ? Kp : 0) + kk;   // A: hi, hi, lo
        const int bk = (t == 1 ? Kp : 0) + kk;   // B: hi, lo, hi
        #pragma unroll
        for (int u = 0; u < 2; u++) {
            const int r = cr0 + u * 64;
            CP_ASYNC16(sb + (uint32_t)r * ROWB + (uint32_t)(cc * 2),
                       g_A2 + (size_t)(m0 + r) * K2 + ak + cc);
        }
        #pragma unroll
        for (int u = 0; u < 2; u++) {
            const int r = cr0 + u * 64;
            CP_ASYNC16(sb + ASZ + (uint32_t)r * ROWB + (uint32_t)(cc * 2),
                       g_B2 + (size_t)(n0 + r) * K2 + bk + cc);
        }
        CP_COMMIT();
    };

    float c[2][8][4];
    #pragma unroll
    for (int i = 0; i < 2; i++)
        #pragma unroll
        for (int j = 0; j < 8; j++)
            #pragma unroll
            for (int q = 0; q < 4; q++) c[i][j][q] = 0.f;

    load_stage(0, 0);
    load_stage(1, 1);

    for (int kt = 0; kt < NKT; kt++) {
        if (kt < NKT - 1) CP_WAIT(1);
        else              CP_WAIT(0);
        __syncthreads();

        if (kt + 2 < NKT) load_stage((kt + 2) % NSTG, kt + 2);

        const uint32_t sA = sbase + (uint32_t)(kt % NSTG) * STAGE;
        const uint32_t sB = sA + ASZ;
        #pragma unroll
        for (int ks = 0; ks < 2; ks++) {
            uint32_t a[2][4], bfr[8][2];
            #pragma unroll
            for (int i = 0; i < 2; i++)
                LDSM_X4(a[i], sA + (uint32_t)((wm * 32 + i * 16) * ROWB) + (uint32_t)(ks * 32) + aoff);
            #pragma unroll
            for (int j2 = 0; j2 < 4; j2++)
                LDSM_X4_B(bfr[j2 * 2][0], bfr[j2 * 2][1],
                          bfr[j2 * 2 + 1][0], bfr[j2 * 2 + 1][1],
                          sB + (uint32_t)((wn * 64 + j2 * 16) * ROWB) + (uint32_t)(ks * 32) + boff);
            #pragma unroll
            for (int i = 0; i < 2; i++)
                #pragma unroll
                for (int j = 0; j < 8; j++)
                    MMA_BF16(c[i][j], a[i], bfr[j]);
        }
    }

    // ---- epilogue: plain [uid][n] store with bias ----
    const int gid = lane >> 2;
    const int tig = lane & 3;
    #pragma unroll
    for (int i = 0; i < 2; i++) {
        const int r0 = m0 + wm * 32 + i * 16 + gid;
        #pragma unroll
        for (int j = 0; j < 8; j++) {
            const int n = n0 + wn * 64 + j * 8 + tig * 2;
            const float bx = __ldg(bias + (n < Dn ? n : 0));
            const float by = __ldg(bias + (n + 1 < Dn ? n + 1 : 0));
            #pragma unroll
            for (int h = 0; h < 2; h++) {
                const int m = r0 + h * 8;
                if (m < cnt) {
                    *reinterpret_cast<float2*>(g_tsu + (size_t)m * Np + n) =
                        make_float2(c[i][j][h * 2] + bx, c[i][j][h * 2 + 1] + by);
                }
            }
        }
    }
}

// ---------------------------------------------------------------------------
// Kernel 2a: chunked max-plus scan with uid indirection + triangular basis.
// Block = (batch, chunk, p-half); threads = patterns (coalesced row reads).
// Slot layout (64 floats): [0..48] M cols j*7+i, [49..55] C, [56..63] S.
// ---------------------------------------------------------------------------
__global__ void __launch_bounds__(128)
scan_part_kernel(const float* __restrict__ epsilon)
{
    const int b   = blockIdx.x;
    const int ch  = blockIdx.y;
    const int ph  = blockIdx.z;
    const int tid = threadIdx.x;

    __shared__ int uids[CL];
    for (int i = tid; i < CL; i += 128)
        uids[i] = g_uid[b * Ln + ch * CL + i];
    __syncthreads();
    if (tid >= PPB) return;
    const int p = ph * PPB + tid;

    float e[6];
    #pragma unroll
    for (int j = 0; j < 6; j++) e[j] = __ldg(epsilon + p * 6 + j);

    float h[8][7];
    #pragma unroll
    for (int j = 0; j < 8; j++)
        #pragma unroll
        for (int i = 0; i < 7; i++) h[j][i] = NINF;
    #pragma unroll
    for (int j = 0; j < 7; j++) h[j][j] = 0.0f;
    float smax[8];
    #pragma unroll
    for (int j = 0; j < 8; j++) smax[j] = NINF;

    const int poff = p * 14;

    float2 nxv[7];
    {
        const float* r = g_tsu + (size_t)uids[0] * Np + poff;
        #pragma unroll
        for (int q = 0; q < 7; q++) nxv[q] = *reinterpret_cast<const float2*>(r + 2 * q);
    }

    for (int l = 0; l < CL; l++) {
        float xv[14];
        #pragma unroll
        for (int q = 0; q < 7; q++) { xv[2 * q] = nxv[q].x; xv[2 * q + 1] = nxv[q].y; }
        if (l + 1 < CL) {
            const float* r = g_tsu + (size_t)uids[l + 1] * Np + poff;
            #pragma unroll
            for (int q = 0; q < 7; q++) nxv[q] = *reinterpret_cast<const float2*>(r + 2 * q);
        }

        // basis columns j = 0..6 (triangular: states < j stay NINF)
        #pragma unroll
        for (int j = 0; j < 7; j++) {
            float nh[7];
            float aeprev = h[j][j];                 // ae[j]
            nh[j] = aeprev + xv[j];                 // pure self-loop at state j
            #pragma unroll
            for (int m = j + 1; m < 7; m++) {
                const float aem = fmaxf(h[j][m], h[j][m - 1] + e[m - 1]);
                nh[m] = fmaxf(aeprev + xv[7 + m - 1], aem + xv[m]);
                aeprev = aem;
            }
            smax[j] = fmaxf(smax[j], nh[6]);
            #pragma unroll
            for (int m = j; m < 7; m++) h[j][m] = nh[m];
        }
        // const column (exact reference semantics incl. restart)
        {
            float ae[7];
            ae[0] = fmaxf(h[7][0], NEG);
            #pragma unroll
            for (int m = 1; m < 7; m++) ae[m] = fmaxf(h[7][m], h[7][m - 1] + e[m - 1]);
            float nh[7];
            nh[0] = fmaxf(0.0f, ae[0] + xv[0]);
            #pragma unroll
            for (int m = 1; m < 7; m++)
                nh[m] = fmaxf(ae[m - 1] + xv[7 + m - 1], ae[m] + xv[m]);
            smax[7] = fmaxf(smax[7], nh[6]);
            #pragma unroll
            for (int m = 0; m < 7; m++) h[7][m] = nh[m];
        }
    }

    float* slot = g_part + ((size_t)(b * Pn + p) * NCH + ch) * 64;
    #pragma unroll
    for (int j = 0; j < 7; j++)
        #pragma unroll
        for (int i = 0; i < 7; i++) slot[j * 7 + i] = (i >= j) ? h[j][i] : NINF;
    #pragma unroll
    for (int i = 0; i < 7; i++) slot[49 + i] = h[7][i];
    #pragma unroll
    for (int j = 0; j < 8; j++) slot[56 + j] = smax[j];
}

// ---------------------------------------------------------------------------
// Kernel 2b: combine the NCH chunk transforms per chain.
// ---------------------------------------------------------------------------
__global__ void scan_combine_kernel()
{
    const int bp = blockIdx.x * blockDim.x + threadIdx.x;
    if (bp >= Bn * Pn) return;

    float h[7];
    h[0] = 0.0f;
    #pragma unroll
    for (int i = 1; i < 7; i++) h[i] = NEG;
    float s = NEG;

    #pragma unroll 1
    for (int c = 0; c < NCH; c++) {
        const float* sl = g_part + ((size_t)bp * NCH + c) * 64;
        float ns = fmaxf(s, sl[63]);
        #pragma unroll
        for (int j = 0; j < 7; j++) ns = fmaxf(ns, sl[56 + j] + h[j]);
        float nh[7];
        #pragma unroll
        for (int i = 0; i < 7; i++) {
            float v = sl[49 + i];
            #pragma unroll
            for (int j = 0; j < 7; j++) v = fmaxf(v, sl[j * 7 + i] + h[j]);
            nh[i] = v;
        }
        #pragma unroll
        for (int i = 0; i < 7; i++) h[i] = nh[i];
        s = ns;
    }
    g_scores[bp] = s;
}

// ---------------------------------------------------------------------------
// Kernel 3: MLP + log_softmax. One block per batch row.
// ---------------------------------------------------------------------------
__global__ void mlp_kernel(const float* __restrict__ w1, const float* __restrict__ b1,
                           const float* __restrict__ w2, const float* __restrict__ b2,
                           const float* __restrict__ w3, const float* __restrict__ b3,
                           float* __restrict__ out)
{
    const int b = blockIdx.x;
    const int tid = threadIdx.x;
    __shared__ float sc[Pn];
    __shared__ float h1[Hn];
    __shared__ float h2[Hn];

    for (int i = tid; i < Pn; i += blockDim.x) sc[i] = g_scores[b * Pn + i];
    __syncthreads();

    if (tid < Hn) {
        float acc = b1[tid];
        #pragma unroll 4
        for (int p = 0; p < Pn; p++) acc = fmaf(sc[p], w1[p * Hn + tid], acc);
        h1[tid] = fmaxf(acc, 0.f);
    }
    __syncthreads();

    if (tid < Hn) {
        float acc = b2[tid];
        #pragma unroll 4
        for (int j = 0; j < Hn; j++) acc = fmaf(h1[j], w2[j * Hn + tid], acc);
        h2[tid] = fmaxf(acc, 0.f);
    }
    __syncthreads();

    if (tid == 0) {
        float l0 = b3[0], l1 = b3[1];
        for (int j = 0; j < Hn; j++) {
            l0 = fmaf(h2[j], w3[j * 2 + 0], l0);
            l1 = fmaf(h2[j], w3[j * 2 + 1], l1);
        }
        float mx  = fmaxf(l0, l1);
        float lse = mx + logf(expf(l0 - mx) + expf(l1 - mx));
        out[b * 2 + 0] = l0 - lse;
        out[b * 2 + 1] = l1 - lse;
    }
}

// ---------------------------------------------------------------------------
extern "C" void kernel_launch(void* const* d_in, const int* in_sizes, int n_in,
                              void* d_out, int out_size)
{
    const int*   docs    = (const int*)  d_in[0];
    const float* emb     = (const float*)d_in[1];
    const float* diags   = (const float*)d_in[2];
    const float* bias    = (const float*)d_in[3];
    const float* epsilon = (const float*)d_in[4];
    const float* w1      = (const float*)d_in[5];
    const float* b1      = (const float*)d_in[6];
    const float* w2      = (const float*)d_in[7];
    const float* b2      = (const float*)d_in[8];
    const float* w3      = (const float*)d_in[9];
    const float* b3      = (const float*)d_in[10];
    float* out = (float*)d_out;

    cudaFuncSetAttribute(gemm_hmma_kernel,
                         cudaFuncAttributeMaxDynamicSharedMemorySize, SMEM_DYN);

    dedup_clear_kernel<<<(Vv + 255) / 256, 256>>>();
    dedup_mark_kernel<<<(Mtot + 255) / 256, 256>>>(docs);
    dedup_scan_kernel<<<1, 1024>>>();
    dedup_uid_kernel<<<(Mtot + 255) / 256, 256>>>(docs);

    conv_emb_kernel<<<Mtot, Kp>>>(emb);
    conv_diag_kernel<<<Np, Kp>>>(diags);

    dim3 gridG(Np / TN, Mtot / TM);   // (22, 256); CTAs beyond count exit
    gemm_hmma_kernel<<<gridG, 256, SMEM_DYN>>>(bias);

    dim3 gridS(Bn, NCH, PSPL);        // (64, 4, 2)
    scan_part_kernel<<<gridS, 128>>>(epsilon);
    scan_combine_kernel<<<(Bn * Pn + 127) / 128, 128>>>();

    mlp_kernel<<<Bn, 128>>>(w1, b1, w2, b2, w3, b3, out);
}